// round 13
// baseline (speedup 1.0000x reference)
#include <cuda_runtime.h>
#include <cstdint>

// Problem constants
constexpr int NB  = 2;
constexpr int NS  = 2048;
constexpr int ND  = 1024;
constexpr int NH  = 16;
constexpr int NHD = 64;
constexpr int NM  = NB * NS;          // 4096 rows

// Scratch (allocation-free rule: device globals)
__device__ float g_q[NM * ND];
__device__ float g_k[NM * ND];
__device__ float g_v[NM * ND];
__device__ float g_att[NM * ND];
__device__ float g_xr[NM * ND];       // tf32-rounded x
__device__ float g_wr[4][ND * ND];    // tf32-rounded Wq,Wk,Wv,Wf

// ---------------------------------------------------------------------------
// helpers
// ---------------------------------------------------------------------------
__device__ __forceinline__ float tf32r(float x) {
    uint32_t u;
    asm("cvt.rna.tf32.f32 %0, %1;" : "=r"(u) : "f"(x));
    return __uint_as_float(u);
}

__device__ __forceinline__ void cpasync16(uint32_t dst, const void* src) {
    asm volatile("cp.async.cg.shared.global [%0], [%1], 16;"
                 :: "r"(dst), "l"(src));
}
__device__ __forceinline__ void cp_commit() {
    asm volatile("cp.async.commit_group;");
}

__device__ __forceinline__ uint32_t smem_u32(const void* p) {
    uint32_t a;
    asm("{ .reg .u64 t; cvta.to.shared.u64 t, %1; cvt.u32.u64 %0, t; }"
        : "=r"(a) : "l"(p));
    return a;
}

__device__ __forceinline__ void mma_tf32(float* d, uint32_t a0, uint32_t a1,
                                         uint32_t a2, uint32_t a3,
                                         uint32_t b0, uint32_t b1) {
    asm volatile(
        "mma.sync.aligned.m16n8k8.row.col.f32.tf32.tf32.f32 "
        "{%0,%1,%2,%3}, {%4,%5,%6,%7}, {%8,%9}, {%0,%1,%2,%3};"
        : "+f"(d[0]), "+f"(d[1]), "+f"(d[2]), "+f"(d[3])
        : "r"(a0), "r"(a1), "r"(a2), "r"(a3), "r"(b0), "r"(b1));
}

// ---------------------------------------------------------------------------
// merged tf32 rounding pass: x (1M float4) then Wq,Wk,Wv,Wf (256K float4 each)
// ---------------------------------------------------------------------------
constexpr int XQ4 = NM * ND / 4;      // 1,048,576
constexpr int WQ4 = ND * ND / 4;      // 262,144 (2^18)

__global__ void round_all(
    const float4* __restrict__ x,
    const float4* __restrict__ wq, const float4* __restrict__ wk,
    const float4* __restrict__ wv, const float4* __restrict__ wf,
    float4* __restrict__ xr, float4* __restrict__ wr)
{
    int i = blockIdx.x * blockDim.x + threadIdx.x;
    const float4* s;
    float4* d;
    int off;
    if (i < XQ4) {
        s = x; d = xr; off = i;
    } else {
        int j = i - XQ4;
        int w = j >> 18;            // / WQ4
        off = j & (WQ4 - 1);
        s = (w == 0) ? wq : (w == 1) ? wk : (w == 2) ? wv : wf;
        d = wr + (size_t)w * WQ4;
    }
    float4 v = s[off];
    v.x = tf32r(v.x); v.y = tf32r(v.y); v.z = tf32r(v.z); v.w = tf32r(v.w);
    d[off] = v;
}

// ---------------------------------------------------------------------------
// tf32 mma.sync GEMM core: Y = X @ W^T + bias
// 2-stage cp.async double-buffer (73.7 KB smem) -> 3 CTAs/SM (24 warps).
// One __syncthreads per chunk: wait_group 0 -> sync -> prefetch(c+1) -> compute.
// B-fragments loaded immediately before use to minimize live registers.
// ---------------------------------------------------------------------------
constexpr int BM = 128, BN = 128, BK = 32, PITCH = 36;
constexpr int TILE_BYTES  = BM * PITCH * 4;      // 18432
constexpr int STAGE_BYTES = 2 * TILE_BYTES;      // 36864
constexpr int GEMM_SMEM   = 2 * STAGE_BYTES;     // 73728
constexpr int NCHUNK = ND / BK;                  // 32

template<bool ROUND>
__device__ __forceinline__ void gemm_body(
    char* dsm, const float* __restrict__ X, const float* __restrict__ W,
    const float* __restrict__ bias, float* __restrict__ Y, int m0, int n0)
{
    const int tid = threadIdx.x;
    const uint32_t sbase = smem_u32(dsm);

    auto load_stage = [&](int j) {
        const uint32_t sb = sbase + (j & 1) * STAGE_BYTES;
        const int k0 = j * BK;
        #pragma unroll
        for (int rr = 0; rr < 4; rr++) {
            int o = tid + 256 * rr;
            int row = o >> 3, ch = o & 7;
            cpasync16(sb + row * (PITCH * 4) + ch * 16,
                      X + (size_t)(m0 + row) * ND + k0 + ch * 4);
        }
        #pragma unroll
        for (int rr = 0; rr < 4; rr++) {
            int o = tid + 256 * rr;
            int row = o >> 3, ch = o & 7;
            cpasync16(sb + TILE_BYTES + row * (PITCH * 4) + ch * 16,
                      W + (size_t)(n0 + row) * ND + k0 + ch * 4);
        }
    };

    load_stage(0); cp_commit();

    const int lane = tid & 31, w = tid >> 5;
    const int wm = (w & 3) * 32, wn = (w >> 2) * 64;
    const int r = lane >> 2, c = lane & 3;

    float acc[2][8][4];
    #pragma unroll
    for (int mi = 0; mi < 2; mi++)
        #pragma unroll
        for (int ni = 0; ni < 8; ni++)
            #pragma unroll
            for (int q = 0; q < 4; q++) acc[mi][ni][q] = 0.f;

    for (int chunk = 0; chunk < NCHUNK; chunk++) {
        asm volatile("cp.async.wait_group 0;" ::: "memory");
        __syncthreads();   // stage `chunk` resident; all warps done with chunk-1
        if (chunk + 1 < NCHUNK) load_stage(chunk + 1);   // writes other buffer
        cp_commit();

        const uint32_t* As = (const uint32_t*)(dsm + (chunk & 1) * STAGE_BYTES);
        const uint32_t* Bs = (const uint32_t*)(dsm + (chunk & 1) * STAGE_BYTES + TILE_BYTES);

        #pragma unroll
        for (int kk = 0; kk < 4; kk++) {
            uint32_t a[2][4];
            #pragma unroll
            for (int mi = 0; mi < 2; mi++) {
                const int row = wm + mi * 16 + r;
                a[mi][0] = As[row * PITCH + kk * 8 + c];
                a[mi][1] = As[(row + 8) * PITCH + kk * 8 + c];
                a[mi][2] = As[row * PITCH + kk * 8 + c + 4];
                a[mi][3] = As[(row + 8) * PITCH + kk * 8 + c + 4];
            }
            #pragma unroll
            for (int ni = 0; ni < 8; ni++) {
                const int rowb = wn + ni * 8 + r;
                uint32_t b0 = Bs[rowb * PITCH + kk * 8 + c];
                uint32_t b1 = Bs[rowb * PITCH + kk * 8 + c + 4];
                mma_tf32(acc[0][ni], a[0][0], a[0][1], a[0][2], a[0][3], b0, b1);
                mma_tf32(acc[1][ni], a[1][0], a[1][1], a[1][2], a[1][3], b0, b1);
            }
        }
    }

    #pragma unroll
    for (int ni = 0; ni < 8; ni++) {
        const int col = n0 + wn + ni * 8 + 2 * c;
        const float2 bv = *(const float2*)&bias[col];
        #pragma unroll
        for (int mi = 0; mi < 2; mi++) {
            const int gr = m0 + wm + mi * 16 + r;
            float2 o0, o1;
            if (ROUND) {
                o0 = make_float2(tf32r(acc[mi][ni][0] + bv.x), tf32r(acc[mi][ni][1] + bv.y));
                o1 = make_float2(tf32r(acc[mi][ni][2] + bv.x), tf32r(acc[mi][ni][3] + bv.y));
            } else {
                o0 = make_float2(acc[mi][ni][0] + bv.x, acc[mi][ni][1] + bv.y);
                o1 = make_float2(acc[mi][ni][2] + bv.x, acc[mi][ni][3] + bv.y);
            }
            *(float2*)&Y[(size_t)gr * ND + col] = o0;
            *(float2*)&Y[(size_t)(gr + 8) * ND + col] = o1;
        }
    }
}

// Fused Q/K/V projection: blockIdx.z selects the weight/bias/output triple.
__global__ __launch_bounds__(256, 3) void gemm_qkv(
    const float* __restrict__ X,
    const float* __restrict__ W0, const float* __restrict__ W1, const float* __restrict__ W2,
    const float* __restrict__ b0, const float* __restrict__ b1, const float* __restrict__ b2,
    float* __restrict__ Y0, float* __restrict__ Y1, float* __restrict__ Y2)
{
    extern __shared__ __align__(16) char dsm[];
    const float* W = (blockIdx.z == 0) ? W0 : (blockIdx.z == 1) ? W1 : W2;
    const float* bb = (blockIdx.z == 0) ? b0 : (blockIdx.z == 1) ? b1 : b2;
    float* Y = (blockIdx.z == 0) ? Y0 : (blockIdx.z == 1) ? Y1 : Y2;
    gemm_body<true>(dsm, X, W, bb, Y, blockIdx.y * BM, blockIdx.x * BN);
}

__global__ __launch_bounds__(256, 3) void gemm_out(
    const float* __restrict__ X, const float* __restrict__ W,
    const float* __restrict__ bias, float* __restrict__ Y)
{
    extern __shared__ __align__(16) char dsm[];
    gemm_body<false>(dsm, X, W, bias, Y, blockIdx.y * BM, blockIdx.x * BN);
}

// ---------------------------------------------------------------------------
// Flash attention, tf32 mma.sync, cp.async 2-stage K/V pipeline.
// (exact R9 mainloop — no diagonal skipping; that predication regressed R10)
// ---------------------------------------------------------------------------
constexpr int AP = 68;
constexpr int ATTN_SMEM = 384 * AP * 4;   // 104448 bytes

__global__ __launch_bounds__(256, 2) void attn_tc(
    const float* __restrict__ Q, const float* __restrict__ Kg,
    const float* __restrict__ V, float* __restrict__ O)
{
    extern __shared__ float sm[];
    float* Qs = sm;                          // rows [0,128)
    const uint32_t sb = smem_u32(sm);

    const int tid = threadIdx.x;
    const int lane = tid & 31, w = tid >> 5;
    const int r = lane >> 2, c = lane & 3;
    const int wm = w * 16;

    const int qt = (int)gridDim.x - 1 - (int)blockIdx.x;   // heavy tiles first
    const int q0 = qt * 128;
    const int bh = blockIdx.y;
    const int b = bh >> 4, h = bh & 15;
    const size_t rowbase = (size_t)b * NS;
    const int coff = h * NHD;

    // Load Q tile once, pre-scaled by exact 0.125 (1/sqrt(64))
    #pragma unroll
    for (int i = 0; i < 8; i++) {
        int o = tid + 256 * i;
        int row = o >> 4, c4 = (o & 15) * 4;
        float4 qv = *(const float4*)&Q[(rowbase + q0 + row) * ND + coff + c4];
        qv.x *= 0.125f; qv.y *= 0.125f; qv.z *= 0.125f; qv.w *= 0.125f;
        *(float4*)&Qs[row * AP + c4] = qv;
    }

    const int kiters = 2 * (qt + 1);

    auto fill_stage = [&](int it) {
        const int s = it & 1;
        const int k0 = it * 64;
        const uint32_t kb = sb + (128 + 64 * s) * AP * 4;
        const uint32_t vb = sb + (256 + 64 * s) * AP * 4;
        #pragma unroll
        for (int i = 0; i < 4; i++) {
            int o = tid + 256 * i;
            int row = o >> 4, ch = o & 15;
            const size_t gro = (rowbase + k0 + row) * ND + coff + ch * 4;
            cpasync16(kb + row * (AP * 4) + ch * 16, Kg + gro);
            cpasync16(vb + row * (AP * 4) + ch * 16, V + gro);
        }
    };

    fill_stage(0); cp_commit();

    float m0v = -1e30f, m1v = -1e30f, l0 = 0.f, l1 = 0.f;
    float oacc[8][4];
    #pragma unroll
    for (int ni = 0; ni < 8; ni++)
        #pragma unroll
        for (int q = 0; q < 4; q++) oacc[ni][q] = 0.f;

    const int row0 = q0 + wm + r, row1 = row0 + 8;
    const int s0lane = 4 * r + (c >> 1);
    const bool sel = (c & 1);

    for (int it = 0; it < kiters; it++) {
        if (it + 1 < kiters) fill_stage(it + 1);
        cp_commit();
        asm volatile("cp.async.wait_group 1;" ::: "memory");
        __syncthreads();   // stage `it` resident CTA-wide

        const int s = it & 1;
        const int k0 = it * 64;
        const uint32_t* Ku = (const uint32_t*)(sm + (size_t)(128 + 64 * s) * AP);
        const uint32_t* Vu = (const uint32_t*)(sm + (size_t)(256 + 64 * s) * AP);
        const uint32_t* Qu = (const uint32_t*)Qs;

        // ---- S[16 x 64] = Qtile @ Ktile^T ----
        float sacc[8][4];
        #pragma unroll
        for (int ni = 0; ni < 8; ni++)
            #pragma unroll
            for (int q = 0; q < 4; q++) sacc[ni][q] = 0.f;

        #pragma unroll
        for (int kk = 0; kk < 8; kk++) {
            uint32_t a0 = Qu[(wm + r) * AP + kk * 8 + c];
            uint32_t a1 = Qu[(wm + r + 8) * AP + kk * 8 + c];
            uint32_t a2 = Qu[(wm + r) * AP + kk * 8 + c + 4];
            uint32_t a3 = Qu[(wm + r + 8) * AP + kk * 8 + c + 4];
            #pragma unroll
            for (int ni = 0; ni < 8; ni++) {
                uint32_t b0 = Ku[(ni * 8 + r) * AP + kk * 8 + c];
                uint32_t b1 = Ku[(ni * 8 + r) * AP + kk * 8 + c + 4];
                mma_tf32(sacc[ni], a0, a1, a2, a3, b0, b1);
            }
        }

        // ---- causal mask (only near diagonal) ----
        if (k0 + 63 > row0) {
            #pragma unroll
            for (int ni = 0; ni < 8; ni++) {
                const int col = k0 + ni * 8 + 2 * c;
                if (col > row0)     sacc[ni][0] = -1e30f;
                if (col + 1 > row0) sacc[ni][1] = -1e30f;
                if (col > row1)     sacc[ni][2] = -1e30f;
                if (col + 1 > row1) sacc[ni][3] = -1e30f;
            }
        }

        // ---- online softmax ----
        float rm0 = -1e30f, rm1 = -1e30f;
        #pragma unroll
        for (int ni = 0; ni < 8; ni++) {
            rm0 = fmaxf(rm0, fmaxf(sacc[ni][0], sacc[ni][1]));
            rm1 = fmaxf(rm1, fmaxf(sacc[ni][2], sacc[ni][3]));
        }
        rm0 = fmaxf(rm0, __shfl_xor_sync(0xffffffffu, rm0, 1));
        rm0 = fmaxf(rm0, __shfl_xor_sync(0xffffffffu, rm0, 2));
        rm1 = fmaxf(rm1, __shfl_xor_sync(0xffffffffu, rm1, 1));
        rm1 = fmaxf(rm1, __shfl_xor_sync(0xffffffffu, rm1, 2));

        const float mn0 = fmaxf(m0v, rm0), mn1 = fmaxf(m1v, rm1);
        const float corr0 = __expf(m0v - mn0), corr1 = __expf(m1v - mn1);
        float rs0 = 0.f, rs1 = 0.f;
        #pragma unroll
        for (int ni = 0; ni < 8; ni++) {
            float p0 = tf32r(__expf(sacc[ni][0] - mn0));
            float p1 = tf32r(__expf(sacc[ni][1] - mn0));
            float p2 = tf32r(__expf(sacc[ni][2] - mn1));
            float p3 = tf32r(__expf(sacc[ni][3] - mn1));
            sacc[ni][0] = p0; sacc[ni][1] = p1; sacc[ni][2] = p2; sacc[ni][3] = p3;
            rs0 += p0 + p1; rs1 += p2 + p3;
        }
        rs0 += __shfl_xor_sync(0xffffffffu, rs0, 1);
        rs0 += __shfl_xor_sync(0xffffffffu, rs0, 2);
        rs1 += __shfl_xor_sync(0xffffffffu, rs1, 1);
        rs1 += __shfl_xor_sync(0xffffffffu, rs1, 2);

        l0 = l0 * corr0 + rs0;  m0v = mn0;
        l1 = l1 * corr1 + rs1;  m1v = mn1;
        #pragma unroll
        for (int ni = 0; ni < 8; ni++) {
            oacc[ni][0] *= corr0; oacc[ni][1] *= corr0;
            oacc[ni][2] *= corr1; oacc[ni][3] *= corr1;
        }

        // ---- O[16 x 64] += P @ V ----
        #pragma unroll
        for (int kk = 0; kk < 8; kk++) {
            float t0 = __shfl_sync(0xffffffffu, sacc[kk][0], s0lane);
            float t1 = __shfl_sync(0xffffffffu, sacc[kk][1], s0lane);
            float t2 = __shfl_sync(0xffffffffu, sacc[kk][2], s0lane);
            float t3 = __shfl_sync(0xffffffffu, sacc[kk][3], s0lane);
            float u0 = __shfl_sync(0xffffffffu, sacc[kk][0], s0lane + 2);
            float u1 = __shfl_sync(0xffffffffu, sacc[kk][1], s0lane + 2);
            float u2 = __shfl_sync(0xffffffffu, sacc[kk][2], s0lane + 2);
            float u3 = __shfl_sync(0xffffffffu, sacc[kk][3], s0lane + 2);
            uint32_t a0 = __float_as_uint(sel ? t1 : t0);
            uint32_t a1 = __float_as_uint(sel ? t3 : t2);
            uint32_t a2 = __float_as_uint(sel ? u1 : u0);
            uint32_t a3 = __float_as_uint(sel ? u3 : u2);
            #pragma unroll
            for (int ni = 0; ni < 8; ni++) {
                uint32_t b0 = Vu[(kk * 8 + c) * AP + ni * 8 + r];
                uint32_t b1 = Vu[(kk * 8 + c + 4) * AP + ni * 8 + r];
                mma_tf32(oacc[ni], a0, a1, a2, a3, b0, b1);
            }
        }
        __syncthreads();   // done reading stage `it`; next iter may overwrite it
    }

    // ---- epilogue: normalize, tf32-round (final GEMM input), store ----
    const float inv0 = 1.f / l0, inv1 = 1.f / l1;
    #pragma unroll
    for (int ni = 0; ni < 8; ni++) {
        const int col = coff + ni * 8 + 2 * c;
        *(float2*)&O[(rowbase + row0) * ND + col] =
            make_float2(tf32r(oacc[ni][0] * inv0), tf32r(oacc[ni][1] * inv0));
        *(float2*)&O[(rowbase + row1) * ND + col] =
            make_float2(tf32r(oacc[ni][2] * inv1), tf32r(oacc[ni][3] * inv1));
    }
}

// ---------------------------------------------------------------------------
extern "C" void kernel_launch(void* const* d_in, const int* in_sizes, int n_in,
                              void* d_out, int out_size)
{
    const float* x  = (const float*)d_in[0];
    const float* Wq = (const float*)d_in[1];
    const float* bq = (const float*)d_in[2];
    const float* Wk = (const float*)d_in[3];
    const float* bk = (const float*)d_in[4];
    const float* Wv = (const float*)d_in[5];
    const float* bv = (const float*)d_in[6];
    const float* Wf = (const float*)d_in[7];
    const float* bf = (const float*)d_in[8];
    float* out = (float*)d_out;

    void *pq, *pk, *pv, *patt, *pxr, *pwr;
    cudaGetSymbolAddress(&pq,   g_q);
    cudaGetSymbolAddress(&pk,   g_k);
    cudaGetSymbolAddress(&pv,   g_v);
    cudaGetSymbolAddress(&patt, g_att);
    cudaGetSymbolAddress(&pxr,  g_xr);
    cudaGetSymbolAddress(&pwr,  g_wr);
    float* xr = (float*)pxr;
    float* wr = (float*)pwr;   // [4][ND*ND]

    cudaFuncSetAttribute(gemm_qkv,
                         cudaFuncAttributeMaxDynamicSharedMemorySize, GEMM_SMEM);
    cudaFuncSetAttribute(gemm_out,
                         cudaFuncAttributeMaxDynamicSharedMemorySize, GEMM_SMEM);
    cudaFuncSetAttribute(attn_tc,
                         cudaFuncAttributeMaxDynamicSharedMemorySize, ATTN_SMEM);

    // tf32-round all GEMM inputs in one launch
    const int total4 = XQ4 + 4 * WQ4;          // 2,097,152
    round_all<<<total4 / 256, 256>>>(
        (const float4*)x, (const float4*)Wq, (const float4*)Wk,
        (const float4*)Wv, (const float4*)Wf, (float4*)xr, (float4*)wr);

    dim3 qkvgrid(ND / BN, NM / BM, 3);   // (8, 32, 3)
    gemm_qkv<<<qkvgrid, 256, GEMM_SMEM>>>(
        xr, wr + 0 * ND * ND, wr + 1 * ND * ND, wr + 2 * ND * ND,
        bq, bk, bv, (float*)pq, (float*)pk, (float*)pv);

    dim3 agrid(NS / 128, NB * NH);       // (16, 32)
    attn_tc<<<agrid, 256, ATTN_SMEM>>>((const float*)pq, (const float*)pk,
                                       (const float*)pv, (float*)patt);

    dim3 ggrid(ND / BN, NM / BM);        // (8, 32)
    gemm_out<<<ggrid, 256, GEMM_SMEM>>>((const float*)patt, wr + 3 * ND * ND, bf, out);
}

// round 14
// speedup vs baseline: 1.2363x; 1.2363x over previous
#include <cuda_runtime.h>
#include <cstdint>

// Problem constants
constexpr int NB  = 2;
constexpr int NS  = 2048;
constexpr int ND  = 1024;
constexpr int NH  = 16;
constexpr int NHD = 64;
constexpr int NM  = NB * NS;          // 4096 rows

// Scratch (allocation-free rule: device globals)
__device__ float g_q[NM * ND];
__device__ float g_k[NM * ND];
__device__ float g_v[NM * ND];
__device__ float g_att[NM * ND];
__device__ float g_xr[NM * ND];       // tf32-rounded x
__device__ float g_wr[4][ND * ND];    // tf32-rounded Wq,Wk,Wv,Wf

// ---------------------------------------------------------------------------
// helpers
// ---------------------------------------------------------------------------
__device__ __forceinline__ float tf32r(float x) {
    uint32_t u;
    asm("cvt.rna.tf32.f32 %0, %1;" : "=r"(u) : "f"(x));
    return __uint_as_float(u);
}

__device__ __forceinline__ void cpasync16(uint32_t dst, const void* src) {
    asm volatile("cp.async.cg.shared.global [%0], [%1], 16;"
                 :: "r"(dst), "l"(src));
}
__device__ __forceinline__ void cp_commit() {
    asm volatile("cp.async.commit_group;");
}

__device__ __forceinline__ uint32_t smem_u32(const void* p) {
    uint32_t a;
    asm("{ .reg .u64 t; cvta.to.shared.u64 t, %1; cvt.u32.u64 %0, t; }"
        : "=r"(a) : "l"(p));
    return a;
}

__device__ __forceinline__ void mma_tf32(float* d, uint32_t a0, uint32_t a1,
                                         uint32_t a2, uint32_t a3,
                                         uint32_t b0, uint32_t b1) {
    asm volatile(
        "mma.sync.aligned.m16n8k8.row.col.f32.tf32.tf32.f32 "
        "{%0,%1,%2,%3}, {%4,%5,%6,%7}, {%8,%9}, {%0,%1,%2,%3};"
        : "+f"(d[0]), "+f"(d[1]), "+f"(d[2]), "+f"(d[3])
        : "r"(a0), "r"(a1), "r"(a2), "r"(a3), "r"(b0), "r"(b1));
}

// ldmatrix x4: loads four 8x4-tf32 (== 8x8 b16) fragment matrices.
// Thread t receives, for each matrix, the 32-bit element (row t/4, col t%4)
// == exactly the m16n8k8 tf32 A/B fragment distribution.
__device__ __forceinline__ void ldsm4(uint32_t* r, uint32_t addr) {
    asm volatile(
        "ldmatrix.sync.aligned.m8n8.x4.shared.b16 {%0,%1,%2,%3}, [%4];"
        : "=r"(r[0]), "=r"(r[1]), "=r"(r[2]), "=r"(r[3]) : "r"(addr));
}

// ---------------------------------------------------------------------------
// merged tf32 rounding pass: x (1M float4) then Wq,Wk,Wv,Wf (256K float4 each)
// ---------------------------------------------------------------------------
constexpr int XQ4 = NM * ND / 4;      // 1,048,576
constexpr int WQ4 = ND * ND / 4;      // 262,144 (2^18)

__global__ void round_all(
    const float4* __restrict__ x,
    const float4* __restrict__ wq, const float4* __restrict__ wk,
    const float4* __restrict__ wv, const float4* __restrict__ wf,
    float4* __restrict__ xr, float4* __restrict__ wr)
{
    int i = blockIdx.x * blockDim.x + threadIdx.x;
    const float4* s;
    float4* d;
    int off;
    if (i < XQ4) {
        s = x; d = xr; off = i;
    } else {
        int j = i - XQ4;
        int w = j >> 18;            // / WQ4
        off = j & (WQ4 - 1);
        s = (w == 0) ? wq : (w == 1) ? wk : (w == 2) ? wv : wf;
        d = wr + (size_t)w * WQ4;
    }
    float4 v = s[off];
    v.x = tf32r(v.x); v.y = tf32r(v.y); v.z = tf32r(v.z); v.w = tf32r(v.w);
    d[off] = v;
}

// ---------------------------------------------------------------------------
// tf32 mma.sync GEMM core: Y = X @ W^T + bias
// 3-stage cp.async pipeline (110.6 KB smem), single sync per chunk.
// Fragment loads via ldmatrix.x4 (24 instr/chunk instead of 96 scalar LDS).
// ---------------------------------------------------------------------------
constexpr int BM = 128, BN = 128, BK = 32, PITCH = 36;
constexpr int TILE_BYTES  = BM * PITCH * 4;      // 18432
constexpr int STAGE_BYTES = 2 * TILE_BYTES;      // 36864
constexpr int GEMM_SMEM   = 3 * STAGE_BYTES;     // 110592
constexpr int NCHUNK = ND / BK;                  // 32

template<bool ROUND>
__device__ __forceinline__ void gemm_body(
    char* dsm, const float* __restrict__ X, const float* __restrict__ W,
    const float* __restrict__ bias, float* __restrict__ Y, int m0, int n0)
{
    const int tid = threadIdx.x;
    const uint32_t sbase = smem_u32(dsm);

    auto load_stage = [&](int j) {
        const uint32_t sb = sbase + (j % 3) * STAGE_BYTES;
        const int k0 = j * BK;
        #pragma unroll
        for (int rr = 0; rr < 4; rr++) {
            int o = tid + 256 * rr;
            int row = o >> 3, ch = o & 7;
            cpasync16(sb + row * (PITCH * 4) + ch * 16,
                      X + (size_t)(m0 + row) * ND + k0 + ch * 4);
        }
        #pragma unroll
        for (int rr = 0; rr < 4; rr++) {
            int o = tid + 256 * rr;
            int row = o >> 3, ch = o & 7;
            cpasync16(sb + TILE_BYTES + row * (PITCH * 4) + ch * 16,
                      W + (size_t)(n0 + row) * ND + k0 + ch * 4);
        }
    };

    load_stage(0); cp_commit();
    load_stage(1); cp_commit();

    const int lane = tid & 31, w = tid >> 5;
    const int wm = (w & 3) * 32, wn = (w >> 2) * 64;
    const int r = lane >> 2, c = lane & 3;
    const int lrow = lane & 7, lm = lane >> 3;

    // ldmatrix per-thread row/col components (constant over chunks):
    //  A mats: {(r,c),(r+8,c),(r,c+4),(r+8,c+4)} -> row = wm+mi*16+(lm&1)*8+lrow,
    //          col = kk*8 + (lm>>1)*4
    //  B mats: {b[2g][0],b[2g][1],b[2g+1][0],b[2g+1][1]} -> row = wn+g*16+(lm>>1)*8+lrow,
    //          col = kk*8 + (lm&1)*4
    const int arow = wm + (lm & 1) * 8 + lrow;
    const int acol = (lm >> 1) * 4;
    const int brow = wn + (lm >> 1) * 8 + lrow;
    const int bcol = (lm & 1) * 4;

    float acc[2][8][4];
    #pragma unroll
    for (int mi = 0; mi < 2; mi++)
        #pragma unroll
        for (int ni = 0; ni < 8; ni++)
            #pragma unroll
            for (int q = 0; q < 4; q++) acc[mi][ni][q] = 0.f;

    for (int chunk = 0; chunk < NCHUNK; chunk++) {
        asm volatile("cp.async.wait_group 1;" ::: "memory");
        __syncthreads();   // stage `chunk` resident; all warps done with chunk-1
        if (chunk + 2 < NCHUNK) load_stage(chunk + 2);  // reuses chunk-1's slot
        cp_commit();

        const uint32_t sa = sbase + (chunk % 3) * STAGE_BYTES;
        const uint32_t sbb = sa + TILE_BYTES;

        #pragma unroll
        for (int kk = 0; kk < 4; kk++) {
            uint32_t a[2][4];
            ldsm4(a[0], sa + (uint32_t)((arow) * PITCH + kk * 8 + acol) * 4);
            ldsm4(a[1], sa + (uint32_t)((arow + 16) * PITCH + kk * 8 + acol) * 4);
            uint32_t b[4][4];
            #pragma unroll
            for (int g = 0; g < 4; g++)
                ldsm4(b[g], sbb + (uint32_t)((brow + g * 16) * PITCH + kk * 8 + bcol) * 4);
            #pragma unroll
            for (int g = 0; g < 4; g++) {
                mma_tf32(acc[0][2 * g],     a[0][0], a[0][1], a[0][2], a[0][3], b[g][0], b[g][1]);
                mma_tf32(acc[1][2 * g],     a[1][0], a[1][1], a[1][2], a[1][3], b[g][0], b[g][1]);
                mma_tf32(acc[0][2 * g + 1], a[0][0], a[0][1], a[0][2], a[0][3], b[g][2], b[g][3]);
                mma_tf32(acc[1][2 * g + 1], a[1][0], a[1][1], a[1][2], a[1][3], b[g][2], b[g][3]);
            }
        }
    }

    #pragma unroll
    for (int ni = 0; ni < 8; ni++) {
        const int col = n0 + wn + ni * 8 + 2 * c;
        const float2 bv = *(const float2*)&bias[col];
        #pragma unroll
        for (int mi = 0; mi < 2; mi++) {
            const int gr = m0 + wm + mi * 16 + r;
            float2 o0, o1;
            if (ROUND) {
                o0 = make_float2(tf32r(acc[mi][ni][0] + bv.x), tf32r(acc[mi][ni][1] + bv.y));
                o1 = make_float2(tf32r(acc[mi][ni][2] + bv.x), tf32r(acc[mi][ni][3] + bv.y));
            } else {
                o0 = make_float2(acc[mi][ni][0] + bv.x, acc[mi][ni][1] + bv.y);
                o1 = make_float2(acc[mi][ni][2] + bv.x, acc[mi][ni][3] + bv.y);
            }
            *(float2*)&Y[(size_t)gr * ND + col] = o0;
            *(float2*)&Y[(size_t)(gr + 8) * ND + col] = o1;
        }
    }
}

// Fused Q/K/V projection: blockIdx.z selects the weight/bias/output triple.
__global__ __launch_bounds__(256) void gemm_qkv(
    const float* __restrict__ X,
    const float* __restrict__ W0, const float* __restrict__ W1, const float* __restrict__ W2,
    const float* __restrict__ b0, const float* __restrict__ b1, const float* __restrict__ b2,
    float* __restrict__ Y0, float* __restrict__ Y1, float* __restrict__ Y2)
{
    extern __shared__ __align__(16) char dsm[];
    const float* W = (blockIdx.z == 0) ? W0 : (blockIdx.z == 1) ? W1 : W2;
    const float* bb = (blockIdx.z == 0) ? b0 : (blockIdx.z == 1) ? b1 : b2;
    float* Y = (blockIdx.z == 0) ? Y0 : (blockIdx.z == 1) ? Y1 : Y2;
    gemm_body<true>(dsm, X, W, bb, Y, blockIdx.y * BM, blockIdx.x * BN);
}

__global__ __launch_bounds__(256) void gemm_out(
    const float* __restrict__ X, const float* __restrict__ W,
    const float* __restrict__ bias, float* __restrict__ Y)
{
    extern __shared__ __align__(16) char dsm[];
    gemm_body<false>(dsm, X, W, bias, Y, blockIdx.y * BM, blockIdx.x * BN);
}

// ---------------------------------------------------------------------------
// Flash attention, tf32 mma.sync, cp.async 2-stage K/V pipeline.
// R9 mainloop; S-phase fragment loads via ldmatrix.x4 (5 instr/kk vs 24 LDS).
// ---------------------------------------------------------------------------
constexpr int AP = 68;
constexpr int ATTN_SMEM = 384 * AP * 4;   // 104448 bytes

__global__ __launch_bounds__(256, 2) void attn_tc(
    const float* __restrict__ Q, const float* __restrict__ Kg,
    const float* __restrict__ V, float* __restrict__ O)
{
    extern __shared__ float sm[];
    float* Qs = sm;                          // rows [0,128)
    const uint32_t sb = smem_u32(sm);

    const int tid = threadIdx.x;
    const int lane = tid & 31, w = tid >> 5;
    const int r = lane >> 2, c = lane & 3;
    const int lrow = lane & 7, lm = lane >> 3;
    const int wm = w * 16;

    const int qt = (int)gridDim.x - 1 - (int)blockIdx.x;   // heavy tiles first
    const int q0 = qt * 128;
    const int bh = blockIdx.y;
    const int b = bh >> 4, h = bh & 15;
    const size_t rowbase = (size_t)b * NS;
    const int coff = h * NHD;

    // ldmatrix row/col components
    const int qrow_l = wm + (lm & 1) * 8 + lrow;   // Q A-frag rows
    const int qcol_l = (lm >> 1) * 4;
    const int krow_l = (lm >> 1) * 8 + lrow;       // K B-frag rows (per g: +16g)
    const int kcol_l = (lm & 1) * 4;

    // Load Q tile once, pre-scaled by exact 0.125 (1/sqrt(64))
    #pragma unroll
    for (int i = 0; i < 8; i++) {
        int o = tid + 256 * i;
        int row = o >> 4, c4 = (o & 15) * 4;
        float4 qv = *(const float4*)&Q[(rowbase + q0 + row) * ND + coff + c4];
        qv.x *= 0.125f; qv.y *= 0.125f; qv.z *= 0.125f; qv.w *= 0.125f;
        *(float4*)&Qs[row * AP + c4] = qv;
    }

    const int kiters = 2 * (qt + 1);

    auto fill_stage = [&](int it) {
        const int s = it & 1;
        const int k0 = it * 64;
        const uint32_t kb = sb + (128 + 64 * s) * AP * 4;
        const uint32_t vb = sb + (256 + 64 * s) * AP * 4;
        #pragma unroll
        for (int i = 0; i < 4; i++) {
            int o = tid + 256 * i;
            int row = o >> 4, ch = o & 15;
            const size_t gro = (rowbase + k0 + row) * ND + coff + ch * 4;
            cpasync16(kb + row * (AP * 4) + ch * 16, Kg + gro);
            cpasync16(vb + row * (AP * 4) + ch * 16, V + gro);
        }
    };

    fill_stage(0); cp_commit();

    float m0v = -1e30f, m1v = -1e30f, l0 = 0.f, l1 = 0.f;
    float oacc[8][4];
    #pragma unroll
    for (int ni = 0; ni < 8; ni++)
        #pragma unroll
        for (int q = 0; q < 4; q++) oacc[ni][q] = 0.f;

    const int row0 = q0 + wm + r, row1 = row0 + 8;
    const int s0lane = 4 * r + (c >> 1);
    const bool sel = (c & 1);

    for (int it = 0; it < kiters; it++) {
        if (it + 1 < kiters) fill_stage(it + 1);
        cp_commit();
        asm volatile("cp.async.wait_group 1;" ::: "memory");
        __syncthreads();   // stage `it` resident CTA-wide

        const int s = it & 1;
        const int k0 = it * 64;
        const uint32_t kbase = sb + (uint32_t)(128 + 64 * s) * AP * 4;
        const uint32_t* Vu = (const uint32_t*)(sm + (size_t)(256 + 64 * s) * AP);

        // ---- S[16 x 64] = Qtile @ Ktile^T ----
        float sacc[8][4];
        #pragma unroll
        for (int ni = 0; ni < 8; ni++)
            #pragma unroll
            for (int q = 0; q < 4; q++) sacc[ni][q] = 0.f;

        #pragma unroll
        for (int kk = 0; kk < 8; kk++) {
            uint32_t aq[4];
            ldsm4(aq, sb + (uint32_t)(qrow_l * AP + kk * 8 + qcol_l) * 4);
            uint32_t bk[4][4];
            #pragma unroll
            for (int g = 0; g < 4; g++)
                ldsm4(bk[g], kbase + (uint32_t)((krow_l + g * 16) * AP + kk * 8 + kcol_l) * 4);
            #pragma unroll
            for (int g = 0; g < 4; g++) {
                mma_tf32(sacc[2 * g],     aq[0], aq[1], aq[2], aq[3], bk[g][0], bk[g][1]);
                mma_tf32(sacc[2 * g + 1], aq[0], aq[1], aq[2], aq[3], bk[g][2], bk[g][3]);
            }
        }

        // ---- causal mask (only near diagonal) ----
        if (k0 + 63 > row0) {
            #pragma unroll
            for (int ni = 0; ni < 8; ni++) {
                const int col = k0 + ni * 8 + 2 * c;
                if (col > row0)     sacc[ni][0] = -1e30f;
                if (col + 1 > row0) sacc[ni][1] = -1e30f;
                if (col > row1)     sacc[ni][2] = -1e30f;
                if (col + 1 > row1) sacc[ni][3] = -1e30f;
            }
        }

        // ---- online softmax ----
        float rm0 = -1e30f, rm1 = -1e30f;
        #pragma unroll
        for (int ni = 0; ni < 8; ni++) {
            rm0 = fmaxf(rm0, fmaxf(sacc[ni][0], sacc[ni][1]));
            rm1 = fmaxf(rm1, fmaxf(sacc[ni][2], sacc[ni][3]));
        }
        rm0 = fmaxf(rm0, __shfl_xor_sync(0xffffffffu, rm0, 1));
        rm0 = fmaxf(rm0, __shfl_xor_sync(0xffffffffu, rm0, 2));
        rm1 = fmaxf(rm1, __shfl_xor_sync(0xffffffffu, rm1, 1));
        rm1 = fmaxf(rm1, __shfl_xor_sync(0xffffffffu, rm1, 2));

        const float mn0 = fmaxf(m0v, rm0), mn1 = fmaxf(m1v, rm1);
        const float corr0 = __expf(m0v - mn0), corr1 = __expf(m1v - mn1);
        float rs0 = 0.f, rs1 = 0.f;
        #pragma unroll
        for (int ni = 0; ni < 8; ni++) {
            float p0 = tf32r(__expf(sacc[ni][0] - mn0));
            float p1 = tf32r(__expf(sacc[ni][1] - mn0));
            float p2 = tf32r(__expf(sacc[ni][2] - mn1));
            float p3 = tf32r(__expf(sacc[ni][3] - mn1));
            sacc[ni][0] = p0; sacc[ni][1] = p1; sacc[ni][2] = p2; sacc[ni][3] = p3;
            rs0 += p0 + p1; rs1 += p2 + p3;
        }
        rs0 += __shfl_xor_sync(0xffffffffu, rs0, 1);
        rs0 += __shfl_xor_sync(0xffffffffu, rs0, 2);
        rs1 += __shfl_xor_sync(0xffffffffu, rs1, 1);
        rs1 += __shfl_xor_sync(0xffffffffu, rs1, 2);

        l0 = l0 * corr0 + rs0;  m0v = mn0;
        l1 = l1 * corr1 + rs1;  m1v = mn1;
        #pragma unroll
        for (int ni = 0; ni < 8; ni++) {
            oacc[ni][0] *= corr0; oacc[ni][1] *= corr0;
            oacc[ni][2] *= corr1; oacc[ni][3] *= corr1;
        }

        // ---- O[16 x 64] += P @ V ----
        #pragma unroll
        for (int kk = 0; kk < 8; kk++) {
            float t0 = __shfl_sync(0xffffffffu, sacc[kk][0], s0lane);
            float t1 = __shfl_sync(0xffffffffu, sacc[kk][1], s0lane);
            float t2 = __shfl_sync(0xffffffffu, sacc[kk][2], s0lane);
            float t3 = __shfl_sync(0xffffffffu, sacc[kk][3], s0lane);
            float u0 = __shfl_sync(0xffffffffu, sacc[kk][0], s0lane + 2);
            float u1 = __shfl_sync(0xffffffffu, sacc[kk][1], s0lane + 2);
            float u2 = __shfl_sync(0xffffffffu, sacc[kk][2], s0lane + 2);
            float u3 = __shfl_sync(0xffffffffu, sacc[kk][3], s0lane + 2);
            uint32_t a0 = __float_as_uint(sel ? t1 : t0);
            uint32_t a1 = __float_as_uint(sel ? t3 : t2);
            uint32_t a2 = __float_as_uint(sel ? u1 : u0);
            uint32_t a3 = __float_as_uint(sel ? u3 : u2);
            #pragma unroll
            for (int ni = 0; ni < 8; ni++) {
                uint32_t b0 = Vu[(kk * 8 + c) * AP + ni * 8 + r];
                uint32_t b1 = Vu[(kk * 8 + c + 4) * AP + ni * 8 + r];
                mma_tf32(oacc[ni], a0, a1, a2, a3, b0, b1);
            }
        }
        __syncthreads();   // done reading stage `it`; next iter may overwrite it
    }

    // ---- epilogue: normalize, tf32-round (final GEMM input), store ----
    const float inv0 = 1.f / l0, inv1 = 1.f / l1;
    #pragma unroll
    for (int ni = 0; ni < 8; ni++) {
        const int col = coff + ni * 8 + 2 * c;
        *(float2*)&O[(rowbase + row0) * ND + col] =
            make_float2(tf32r(oacc[ni][0] * inv0), tf32r(oacc[ni][1] * inv0));
        *(float2*)&O[(rowbase + row1) * ND + col] =
            make_float2(tf32r(oacc[ni][2] * inv1), tf32r(oacc[ni][3] * inv1));
    }
}

// ---------------------------------------------------------------------------
extern "C" void kernel_launch(void* const* d_in, const int* in_sizes, int n_in,
                              void* d_out, int out_size)
{
    const float* x  = (const float*)d_in[0];
    const float* Wq = (const float*)d_in[1];
    const float* bq = (const float*)d_in[2];
    const float* Wk = (const float*)d_in[3];
    const float* bk = (const float*)d_in[4];
    const float* Wv = (const float*)d_in[5];
    const float* bv = (const float*)d_in[6];
    const float* Wf = (const float*)d_in[7];
    const float* bf = (const float*)d_in[8];
    float* out = (float*)d_out;

    void *pq, *pk, *pv, *patt, *pxr, *pwr;
    cudaGetSymbolAddress(&pq,   g_q);
    cudaGetSymbolAddress(&pk,   g_k);
    cudaGetSymbolAddress(&pv,   g_v);
    cudaGetSymbolAddress(&patt, g_att);
    cudaGetSymbolAddress(&pxr,  g_xr);
    cudaGetSymbolAddress(&pwr,  g_wr);
    float* xr = (float*)pxr;
    float* wr = (float*)pwr;   // [4][ND*ND]

    cudaFuncSetAttribute(gemm_qkv,
                         cudaFuncAttributeMaxDynamicSharedMemorySize, GEMM_SMEM);
    cudaFuncSetAttribute(gemm_out,
                         cudaFuncAttributeMaxDynamicSharedMemorySize, GEMM_SMEM);
    cudaFuncSetAttribute(attn_tc,
                         cudaFuncAttributeMaxDynamicSharedMemorySize, ATTN_SMEM);

    // tf32-round all GEMM inputs in one launch
    const int total4 = XQ4 + 4 * WQ4;          // 2,097,152
    round_all<<<total4 / 256, 256>>>(
        (const float4*)x, (const float4*)Wq, (const float4*)Wk,
        (const float4*)Wv, (const float4*)Wf, (float4*)xr, (float4*)wr);

    dim3 qkvgrid(ND / BN, NM / BM, 3);   // (8, 32, 3)
    gemm_qkv<<<qkvgrid, 256, GEMM_SMEM>>>(
        xr, wr + 0 * ND * ND, wr + 1 * ND * ND, wr + 2 * ND * ND,
        bq, bk, bv, (float*)pq, (float*)pk, (float*)pv);

    dim3 agrid(NS / 128, NB * NH);       // (16, 32)
    attn_tc<<<agrid, 256, ATTN_SMEM>>>((const float*)pq, (const float*)pk,
                                       (const float*)pv, (float*)patt);

    dim3 ggrid(ND / BN, NM / BM);        // (8, 32)
    gemm_out<<<ggrid, 256, GEMM_SMEM>>>((const float*)patt, wr + 3 * ND * ND, bf, out);
}